// round 3
// baseline (speedup 1.0000x reference)
#include <cuda_runtime.h>
#include <cuda_bf16.h>

// Problem shape (fixed per problem instance)
#define B_MAX 16
#define S_DIM 4096
#define D_DIM 512
#define D4 (D_DIM / 4)                       // 128 float4 per row
#define NCHUNK 32                            // row chunks per batch
#define ROWS_PER_CHUNK (S_DIM / NCHUNK)      // 128
#define THREADS 128                          // one float4 column-slot per thread

// Deterministic partial-sum scratch: [B][NCHUNK][D] floats = 1 MiB (L2-resident)
__device__ float4 g_scratch[B_MAX * NCHUNK * D4];
// Per-batch completion counters (statically zeroed; reset by the finishing CTA
// so every graph replay starts from 0).
__device__ unsigned int g_count[B_MAX];

// xs_len may be int32 (JAX x64-disabled downcast) or int64.
// Little-endian sniff: word[1] is the high half of len[0] if int64 (== 0,
// since len <= 4096), or len[1] if int32 (in [1,4096], != 0).
__device__ __forceinline__ long long read_len(const void* p, int b)
{
    const int* p32 = (const int*)p;
    if (p32[1] == 0) {
        return ((const long long*)p)[b];   // int64 layout
    } else {
        return (long long)p32[b];          // int32 layout
    }
}

__global__ __launch_bounds__(THREADS)
void mean_fused_kernel(const float* __restrict__ xs,
                       const void* __restrict__ xs_len,
                       float* __restrict__ out)
{
    const int chunk = blockIdx.x;        // 0..NCHUNK-1
    const int b     = blockIdx.y;        // 0..B-1
    const int t     = threadIdx.x;       // 0..127 -> float4 column slot

    const long long L = read_len(xs_len, b);
    const int r0 = chunk * ROWS_PER_CHUNK;
    int r1 = r0 + ROWS_PER_CHUNK;
    if ((long long)r1 > L) r1 = (int)L;

    float4 acc = make_float4(0.f, 0.f, 0.f, 0.f);

    if (r0 < r1) {
        const float4* base = reinterpret_cast<const float4*>(
            xs + (size_t)b * S_DIM * D_DIM) + t;

        float4 a0 = make_float4(0.f, 0.f, 0.f, 0.f);
        float4 a1 = make_float4(0.f, 0.f, 0.f, 0.f);
        float4 a2 = make_float4(0.f, 0.f, 0.f, 0.f);
        float4 a3 = make_float4(0.f, 0.f, 0.f, 0.f);

        int r = r0;
        // 4-row unroll: 4 independent LDG.128 in flight per thread (MLP>=4)
        for (; r + 4 <= r1; r += 4) {
            float4 v0 = base[(size_t)(r + 0) * D4];
            float4 v1 = base[(size_t)(r + 1) * D4];
            float4 v2 = base[(size_t)(r + 2) * D4];
            float4 v3 = base[(size_t)(r + 3) * D4];
            a0.x += v0.x; a0.y += v0.y; a0.z += v0.z; a0.w += v0.w;
            a1.x += v1.x; a1.y += v1.y; a1.z += v1.z; a1.w += v1.w;
            a2.x += v2.x; a2.y += v2.y; a2.z += v2.z; a2.w += v2.w;
            a3.x += v3.x; a3.y += v3.y; a3.z += v3.z; a3.w += v3.w;
        }
        for (; r < r1; r++) {
            float4 v = base[(size_t)r * D4];
            a0.x += v.x; a0.y += v.y; a0.z += v.z; a0.w += v.w;
        }

        acc.x = (a0.x + a1.x) + (a2.x + a3.x);
        acc.y = (a0.y + a1.y) + (a2.y + a3.y);
        acc.z = (a0.z + a1.z) + (a2.z + a3.z);
        acc.w = (a0.w + a1.w) + (a2.w + a3.w);
    }

    g_scratch[(b * NCHUNK + chunk) * D4 + t] = acc;

    // ---- last-CTA-done handoff (threadFenceReduction pattern) ----
    __threadfence();           // make scratch writes visible device-wide
    __shared__ bool am_last;
    __syncthreads();           // all threads' scratch stores issued before arrive
    if (t == 0) {
        unsigned int prev = atomicInc(&g_count[b], NCHUNK - 1);
        am_last = (prev == NCHUNK - 1);   // atomicInc wraps to 0 at NCHUNK-1
    }
    __syncthreads();

    if (am_last) {
        __threadfence();       // acquire side: see all other CTAs' partials

        float4 s = make_float4(0.f, 0.f, 0.f, 0.f);
        const float4* src = &g_scratch[b * NCHUNK * D4 + t];
        #pragma unroll
        for (int c = 0; c < NCHUNK; c++) {
            float4 v = src[c * D4];
            s.x += v.x; s.y += v.y; s.z += v.z; s.w += v.w;
        }

        const float inv = 1.0f / (float)L;
        s.x *= inv; s.y *= inv; s.z *= inv; s.w *= inv;

        reinterpret_cast<float4*>(out + (size_t)b * D_DIM)[t] = s;
        // counter already wrapped to 0 by atomicInc -> ready for next replay
    }
}

extern "C" void kernel_launch(void* const* d_in, const int* in_sizes, int n_in,
                              void* d_out, int out_size)
{
    const float* xs     = (const float*)d_in[0];
    const void*  xs_len = d_in[1];
    float*       out    = (float*)d_out;

    const int B = in_sizes[1];   // number of sequences (16)

    dim3 grid(NCHUNK, B);
    mean_fused_kernel<<<grid, THREADS>>>(xs, xs_len, out);
}

// round 6
// speedup vs baseline: 1.1212x; 1.1212x over previous
#include <cuda_runtime.h>
#include <cuda_bf16.h>

// Problem shape (fixed per problem instance)
#define B_MAX 16
#define S_DIM 4096
#define D_DIM 512
#define D4 (D_DIM / 4)                       // 128 float4 per row
#define NCHUNK 64                            // row chunks per batch
#define ROWS_PER_CHUNK (S_DIM / NCHUNK)      // 64
#define THREADS 128                          // one float4 column-slot per thread

// Deterministic partial-sum scratch: [B][NCHUNK][D] floats = 2 MiB (L2-resident)
__device__ float4 g_scratch[B_MAX * NCHUNK * D4];

// xs_len may be int32 (JAX x64-disabled downcast) or int64.
// Little-endian sniff: word[1] is the high half of len[0] if int64 (== 0,
// since len <= 4096), or len[1] if int32 (in [1,4096], != 0).
__device__ __forceinline__ long long read_len(const void* p, int b)
{
    const int* p32 = (const int*)p;
    if (p32[1] == 0) {
        return ((const long long*)p)[b];   // int64 layout
    } else {
        return (long long)p32[b];          // int32 layout
    }
}

__global__ __launch_bounds__(THREADS)
void mean_accum_kernel(const float* __restrict__ xs,
                       const void* __restrict__ xs_len)
{
    const int chunk = blockIdx.x;        // 0..NCHUNK-1
    const int b     = blockIdx.y;        // 0..B-1
    const int t     = threadIdx.x;       // 0..127 -> float4 column slot

    const long long L = read_len(xs_len, b);
    const int r0 = chunk * ROWS_PER_CHUNK;
    int r1 = r0 + ROWS_PER_CHUNK;
    if ((long long)r1 > L) r1 = (int)L;

    float4* outp = &g_scratch[(b * NCHUNK + chunk) * D4 + t];

    if (r0 >= r1) {
        *outp = make_float4(0.f, 0.f, 0.f, 0.f);
        return;
    }

    const float4* base = reinterpret_cast<const float4*>(
        xs + (size_t)b * S_DIM * D_DIM) + t;

    float4 a0 = make_float4(0.f, 0.f, 0.f, 0.f);
    float4 a1 = make_float4(0.f, 0.f, 0.f, 0.f);
    float4 a2 = make_float4(0.f, 0.f, 0.f, 0.f);
    float4 a3 = make_float4(0.f, 0.f, 0.f, 0.f);

    int r = r0;
    // 8 independent LDG.128 front-batched per iteration -> MLP ~8/thread
    for (; r + 8 <= r1; r += 8) {
        float4 v0 = base[(size_t)(r + 0) * D4];
        float4 v1 = base[(size_t)(r + 1) * D4];
        float4 v2 = base[(size_t)(r + 2) * D4];
        float4 v3 = base[(size_t)(r + 3) * D4];
        float4 v4 = base[(size_t)(r + 4) * D4];
        float4 v5 = base[(size_t)(r + 5) * D4];
        float4 v6 = base[(size_t)(r + 6) * D4];
        float4 v7 = base[(size_t)(r + 7) * D4];
        a0.x += v0.x; a0.y += v0.y; a0.z += v0.z; a0.w += v0.w;
        a1.x += v1.x; a1.y += v1.y; a1.z += v1.z; a1.w += v1.w;
        a2.x += v2.x; a2.y += v2.y; a2.z += v2.z; a2.w += v2.w;
        a3.x += v3.x; a3.y += v3.y; a3.z += v3.z; a3.w += v3.w;
        a0.x += v4.x; a0.y += v4.y; a0.z += v4.z; a0.w += v4.w;
        a1.x += v5.x; a1.y += v5.y; a1.z += v5.z; a1.w += v5.w;
        a2.x += v6.x; a2.y += v6.y; a2.z += v6.z; a2.w += v6.w;
        a3.x += v7.x; a3.y += v7.y; a3.z += v7.z; a3.w += v7.w;
    }
    for (; r < r1; r++) {
        float4 v = base[(size_t)r * D4];
        a0.x += v.x; a0.y += v.y; a0.z += v.z; a0.w += v.w;
    }

    float4 acc;
    acc.x = (a0.x + a1.x) + (a2.x + a3.x);
    acc.y = (a0.y + a1.y) + (a2.y + a3.y);
    acc.z = (a0.z + a1.z) + (a2.z + a3.z);
    acc.w = (a0.w + a1.w) + (a2.w + a3.w);

    *outp = acc;
}

// grid (4, B), block 128. Each CTA reduces 32 float4 columns.
// Thread layout: col_local = t & 31, stripe = t >> 5 (4 stripes).
// Each thread sums 16 contiguous chunks; stripes combined in fixed order
// via smem -> fully deterministic.
__global__ __launch_bounds__(THREADS)
void mean_finish_kernel(const void* __restrict__ xs_len,
                        float* __restrict__ out)
{
    const int b         = blockIdx.y;
    const int col       = blockIdx.x * 32 + (threadIdx.x & 31);
    const int stripe    = threadIdx.x >> 5;          // 0..3
    const int c0        = stripe * (NCHUNK / 4);     // 16 chunks per stripe

    __shared__ float4 smem[4][32];

    float4 s = make_float4(0.f, 0.f, 0.f, 0.f);
    const float4* src = &g_scratch[(b * NCHUNK + c0) * D4 + col];
    #pragma unroll
    for (int c = 0; c < NCHUNK / 4; c++) {
        float4 v = src[c * D4];
        s.x += v.x; s.y += v.y; s.z += v.z; s.w += v.w;
    }

    smem[stripe][threadIdx.x & 31] = s;
    __syncthreads();

    if (stripe == 0) {
        float4 s0 = smem[0][threadIdx.x & 31];
        float4 s1 = smem[1][threadIdx.x & 31];
        float4 s2 = smem[2][threadIdx.x & 31];
        float4 s3 = smem[3][threadIdx.x & 31];
        float4 tot;
        tot.x = (s0.x + s1.x) + (s2.x + s3.x);
        tot.y = (s0.y + s1.y) + (s2.y + s3.y);
        tot.z = (s0.z + s1.z) + (s2.z + s3.z);
        tot.w = (s0.w + s1.w) + (s2.w + s3.w);

        const float inv = 1.0f / (float)read_len(xs_len, b);
        tot.x *= inv; tot.y *= inv; tot.z *= inv; tot.w *= inv;

        reinterpret_cast<float4*>(out + (size_t)b * D_DIM)[col] = tot;
    }
}

extern "C" void kernel_launch(void* const* d_in, const int* in_sizes, int n_in,
                              void* d_out, int out_size)
{
    const float* xs     = (const float*)d_in[0];
    const void*  xs_len = d_in[1];
    float*       out    = (float*)d_out;

    const int B = in_sizes[1];   // number of sequences (16)

    dim3 grid1(NCHUNK, B);
    mean_accum_kernel<<<grid1, THREADS>>>(xs, xs_len);

    dim3 grid2(4, B);
    mean_finish_kernel<<<grid2, THREADS>>>(xs_len, out);
}